// round 1
// baseline (speedup 1.0000x reference)
#include <cuda_runtime.h>

// ---------------- problem constants ----------------
#define TT   4
#define BB   8
#define NN   32        // T*B
#define CIN  256
#define HH   64
#define WW   64
#define HW   4096
#define K1   192       // conv1 out channels
#define K2   320       // conv2 out channels
#define GRPS 4
#define CG   48        // in channels per group (192/4)
#define KG   80        // out channels per group (320/4)
#define OUTC 512       // K1 + K2

// ---------------- scratch (device globals; no allocation allowed) ----------------
__device__ float g_spikes[(size_t)NN * CIN * HW];   // 134 MB
__device__ float g_y     [(size_t)NN * K1  * HW];   // 100 MB
__device__ float g_yb    [(size_t)NN * K1  * HW];   // 100 MB
__device__ float g_psum  [K1 * NN];                 // BN partial sums (deterministic)
__device__ float g_psq   [K1 * NN];
__device__ float g_mean  [K1];
__device__ float g_istd  [K1];

// ---------------- LIF: v' = v + (x - v)/2 ; s = (v' >= 1); v'' = v' - s ----------------
__global__ void lif_kernel(const float* __restrict__ x) {
    int idx = blockIdx.x * blockDim.x + threadIdx.x;   // over B*CIN*HW = 8388608
    if (idx >= BB * CIN * HW) return;
    float v = 0.0f;
    #pragma unroll
    for (int t = 0; t < TT; t++) {
        float xv = x[(size_t)t * (BB * CIN * HW) + idx];
        v = v + (xv - v) * 0.5f;                 // matches reference rounding exactly
        float s = (v >= 1.0f) ? 1.0f : 0.0f;
        v -= s;                                  // VTH = 1
        g_spikes[(size_t)t * (BB * CIN * HW) + idx] = s;
    }
}

// ---------------- generic 3x3 conv body: 16 oc x (8 rows x 64 cols) per block ----------------
// 128 threads: thread = (oc_half 0..1) x (strip 0..63); strip -> (row 0..7, col0 = 8*(strip&7))
// Per thread: acc[8 oc][8 px]
template <int CC, bool SIGNW>
__device__ __forceinline__ void conv_body(
    const float* __restrict__ in,   // base [cin][HW] for this (n[,group])
    const float* __restrict__ w,    // base for this oc tile: layout [o_local][cin][3][3]
    int cin,
    float* __restrict__ out,        // base for this (n, oc tile): stride HW per channel
    int row0)
{
    __shared__ float s_in[CC][10][66];
    __shared__ float s_w [CC][9][16];

    const int tid    = threadIdx.x;
    const int strip  = tid & 63;
    const int ochalf = tid >> 6;
    const int prow   = strip >> 3;
    const int pcol0  = (strip & 7) * 8;
    const int ocb    = ochalf * 8;

    float acc[8][8];
    #pragma unroll
    for (int o = 0; o < 8; o++)
        #pragma unroll
        for (int p = 0; p < 8; p++) acc[o][p] = 0.0f;

    for (int c0 = 0; c0 < cin; c0 += CC) {
        // load input tile: rows row0-1..row0+8, cols -1..64, CC channels (zero-padded)
        for (int i = tid; i < CC * 10 * 66; i += 128) {
            int cc  = i / 660;
            int rem = i - cc * 660;
            int r   = rem / 66;
            int col = rem - r * 66;
            int gr = row0 - 1 + r;
            int gc = col - 1;
            float v = 0.0f;
            if (gr >= 0 && gr < HH && gc >= 0 && gc < WW)
                v = in[(size_t)(c0 + cc) * HW + gr * WW + gc];
            s_in[cc][r][col] = v;
        }
        // load weights: CC x 9 taps x 16 oc
        for (int i = tid; i < CC * 9 * 16; i += 128) {
            int cc  = i / 144;
            int rem = i - cc * 144;
            int tap = rem >> 4;
            int o   = rem & 15;
            float wv = w[((size_t)o * cin + (c0 + cc)) * 9 + tap];
            if (SIGNW) wv = (wv > 0.0f) ? 1.0f : ((wv < 0.0f) ? -1.0f : 0.0f);
            s_w[cc][tap][o] = wv;
        }
        __syncthreads();

        #pragma unroll
        for (int cc = 0; cc < CC; cc++) {
            #pragma unroll
            for (int ky = 0; ky < 3; ky++) {
                float inv[10];
                #pragma unroll
                for (int j = 0; j < 10; j++)
                    inv[j] = s_in[cc][prow + ky][pcol0 + j];
                #pragma unroll
                for (int kx = 0; kx < 3; kx++) {
                    float wv[8];
                    #pragma unroll
                    for (int o = 0; o < 8; o++)
                        wv[o] = s_w[cc][ky * 3 + kx][ocb + o];
                    #pragma unroll
                    for (int o = 0; o < 8; o++)
                        #pragma unroll
                        for (int p = 0; p < 8; p++)
                            acc[o][p] += wv[o] * inv[p + kx];
                }
            }
        }
        __syncthreads();
    }

    // write 16 oc x 8x64 tile
    #pragma unroll
    for (int o = 0; o < 8; o++) {
        float* op = out + (size_t)(ocb + o) * HW + (row0 + prow) * WW + pcol0;
        #pragma unroll
        for (int p = 0; p < 8; p++) op[p] = acc[o][p];
    }
}

__global__ void __launch_bounds__(128) conv1_kernel(const float* __restrict__ w1) {
    int n = blockIdx.z, oct = blockIdx.y, rt = blockIdx.x;
    conv_body<4, false>(
        g_spikes + (size_t)n * CIN * HW,
        w1 + (size_t)oct * 16 * CIN * 9,
        CIN,
        g_y + ((size_t)n * K1 + oct * 16) * HW,
        rt * 8);
}

__global__ void __launch_bounds__(128) conv2_kernel(const float* __restrict__ w2,
                                                    float* __restrict__ out) {
    int n = blockIdx.z, y = blockIdx.y, rt = blockIdx.x;
    int g = y / 5, oct = y - g * 5;
    int obase = g * KG + oct * 16;
    conv_body<4, true>(
        g_yb + ((size_t)n * K1 + g * CG) * HW,
        w2 + (size_t)obase * CG * 9,
        CG,
        out + ((size_t)n * OUTC + K1 + obase) * HW,
        rt * 8);
}

// ---------------- BN: deterministic two-stage reduction ----------------
__global__ void bn_reduce() {
    int k = blockIdx.x;   // channel
    int n = blockIdx.y;   // image
    const float* p = g_y + ((size_t)n * K1 + k) * HW;
    float s = 0.0f, s2 = 0.0f;
    for (int i = threadIdx.x; i < HW; i += 256) {
        float v = p[i];
        s += v; s2 += v * v;
    }
    __shared__ float rs[256], rq[256];
    rs[threadIdx.x] = s; rq[threadIdx.x] = s2;
    __syncthreads();
    for (int off = 128; off > 0; off >>= 1) {
        if (threadIdx.x < off) {
            rs[threadIdx.x] += rs[threadIdx.x + off];
            rq[threadIdx.x] += rq[threadIdx.x + off];
        }
        __syncthreads();
    }
    if (threadIdx.x == 0) {
        g_psum[k * NN + n] = rs[0];
        g_psq [k * NN + n] = rq[0];
    }
}

__global__ void bn_finalize() {
    int k = threadIdx.x;
    if (k < K1) {
        float s = 0.0f, s2 = 0.0f;
        for (int n = 0; n < NN; n++) { s += g_psum[k * NN + n]; s2 += g_psq[k * NN + n]; }
        const float cnt = (float)(NN * HW);
        float m = s / cnt;
        float var = s2 / cnt - m * m;       // biased variance
        g_mean[k] = m;
        g_istd[k] = rsqrtf(var + 1e-5f);
    }
}

// apply BN; write x1 slice of output and yb scratch (conv2 input)
__global__ void bn_apply(const float* __restrict__ gamma,
                         const float* __restrict__ beta,
                         float* __restrict__ out) {
    int nk = blockIdx.y;                    // n*K1 + k   (0..6143)
    int k  = nk % K1;
    int n  = nk / K1;
    int hw = blockIdx.x * 256 + threadIdx.x;
    float v = g_y[(size_t)nk * HW + hw];
    float r = (v - g_mean[k]) * g_istd[k] * gamma[k] + beta[k];
    g_yb[(size_t)nk * HW + hw] = r;
    out[((size_t)n * OUTC + k) * HW + hw] = r;
}

// ---------------- launch ----------------
extern "C" void kernel_launch(void* const* d_in, const int* in_sizes, int n_in,
                              void* d_out, int out_size) {
    const float* x     = (const float*)d_in[0];
    const float* w1    = (const float*)d_in[1];
    const float* gamma = (const float*)d_in[2];
    const float* beta  = (const float*)d_in[3];
    const float* w2    = (const float*)d_in[4];
    float* out = (float*)d_out;

    lif_kernel<<<(BB * CIN * HW) / 256, 256>>>(x);

    conv1_kernel<<<dim3(8, 12, 32), 128>>>(w1);          // -> g_y

    bn_reduce  <<<dim3(K1, NN), 256>>>();
    bn_finalize<<<1, K1>>>();
    bn_apply   <<<dim3(HW / 256, NN * K1), 256>>>(gamma, beta, out);  // -> x1 + g_yb

    conv2_kernel<<<dim3(8, 20, 32), 128>>>(w2, out);      // -> x2
}